// round 16
// baseline (speedup 1.0000x reference)
#include <cuda_runtime.h>
#include <cuda_bf16.h>

typedef unsigned int u32;
typedef unsigned long long u64;
typedef unsigned char u8;

#define BATCH 16384
#define NOUT  128
#define LH    64
#define NPRED 25

// ---------------- scratch ----------------
__device__ u64 gTicket;                 // monotonic grid-barrier ticket (zero-init)
__device__ float g_part1[128 * 64];
__device__ float g_part2[128 * 64];
// bf16-split weights, col interleave n = 32*(q>>3) + 8*gate + (q&7)
__device__ u8 g_Wih_sw[65536];
__device__ u8 g_Wc_sw [65536];

// ---------------- helpers ----------------
__device__ __forceinline__ u64 pk2(float a, float b) {
    u64 r; asm("mov.b64 %0,{%1,%2};" : "=l"(r) : "f"(a), "f"(b)); return r;
}
__device__ __forceinline__ void upk2(u64 v, float &a, float &b) {
    asm("mov.b64 {%0,%1},%2;" : "=f"(a), "=f"(b) : "l"(v));
}
__device__ __forceinline__ void ffma2(u64 &d, u64 a, u64 b) {
    asm("fma.rn.f32x2 %0,%1,%2,%0;" : "+l"(d) : "l"(a), "l"(b));
}
__device__ __forceinline__ float tanhfast(float x) {
    float r; asm("tanh.approx.f32 %0,%1;" : "=f"(r) : "f"(x)); return r;
}
__device__ __forceinline__ u32 smem_u32(const void* p) {
    u32 a; asm("{ .reg .u64 t; cvta.to.shared.u64 t, %1; cvt.u32.u64 %0, t; }"
               : "=r"(a) : "l"(p));
    return a;
}
__device__ __forceinline__ void comb4(u64 &acc) {
    u64 o = __shfl_xor_sync(0xffffffffu, acc, 1);
    float a0, a1, b0, b1;
    upk2(acc, a0, a1); upk2(o, b0, b1);
    acc = pk2(a0 + b0, a1 + b1);
    o = __shfl_xor_sync(0xffffffffu, acc, 2);
    upk2(acc, a0, a1); upk2(o, b0, b1);
    acc = pk2(a0 + b0, a1 + b1);
}

#define LDSM4(r0, r1, r2, r3, addr) \
    asm volatile("ldmatrix.sync.aligned.m8n8.x4.shared.b16 {%0,%1,%2,%3}, [%4];" \
        : "=r"(r0), "=r"(r1), "=r"(r2), "=r"(r3) : "r"(addr))

#define MMA16816(d, a0, a1, a2, a3, b0, b1) \
    asm volatile("mma.sync.aligned.m16n8k16.row.col.f32.bf16.bf16.f32 " \
        "{%0,%1,%2,%3}, {%4,%5,%6,%7}, {%8,%9}, {%0,%1,%2,%3};" \
        : "+f"((d)[0]), "+f"((d)[1]), "+f"((d)[2]), "+f"((d)[3]) \
        : "r"(a0), "r"(a1), "r"(a2), "r"(a3), "r"(b0), "r"(b1))

#define BAR_HALF(id) \
    asm volatile("bar.sync %0, 256;" :: "r"(id) : "memory")

// grid-wide barrier: all 128 blocks co-resident (1 block/SM, grid <= SMs).
// Monotonic ticket; target = next multiple of 128 -> correct across replays.
__device__ __forceinline__ void grid_sync(int tid) {
    __syncthreads();
    if (tid == 0) {
        __threadfence();
        u64 t = atomicAdd(&gTicket, 1ULL);
        u64 target = ((t >> 7) + 1ULL) << 7;
        u64 cur;
        do {
            asm volatile("ld.volatile.global.u64 %0, [%1];" : "=l"(cur) : "l"(&gTicket));
        } while (cur < target);
        __threadfence();
    }
    __syncthreads();
}

// n-col -> original weight row mapping (shuffle-free epilogue layout)
__device__ __forceinline__ int n_to_row(int n) {
    int gate = (n >> 3) & 3;
    int q = ((n >> 5) << 3) + (n & 7);
    return gate * 64 + q;
}

__device__ __forceinline__ void prep_one(int idx, const float* __restrict__ Wih,
                                         const float* __restrict__ Whh)
{
    int n = idx >> 7;
    int k = idx & 127;
    int r = n_to_row(n);
    int ks = k & 63;
    float wih = Wih[r * 64 + ks];
    float wc  = wih + Whh[r * 64 + ks];
    bool lo = (k >= 64);
    __nv_bfloat16 vih, vc;
    {
        __nv_bfloat16 hi = __float2bfloat16_rn(wih);
        vih = lo ? __float2bfloat16_rn(wih - __bfloat162float(hi)) : hi;
    }
    {
        __nv_bfloat16 hi = __float2bfloat16_rn(wc);
        vc = lo ? __float2bfloat16_rn(wc - __bfloat162float(hi)) : hi;
    }
    int off = n * 256 + k * 2;
    off ^= (n & 7) << 4;
    *(__nv_bfloat16*)(g_Wih_sw + off) = vih;
    *(__nv_bfloat16*)(g_Wc_sw  + off) = vc;
}

// =====================================================================
// smem map (one 173056-B block):
//  SW_OFF  [0,65536)      : phase A: W1 floats (49216 B) ; phase D: Wih/Wc
//  SA0_OFF [65536,98304)  : phase A-B: A1 (16 KB)        ; phase C+: A-tile buf0 (m-split)
//          [98304,131072) : phase B-C: A2 at +32768 (16KB); LSTM A-tile buf1
//  SC_OFF  [131072,172032): phases A-C: BN scratch        ; LSTM c-state
//  SBC_OFF [172032,173056): LSTM biases
// =====================================================================
#define SW_OFF  0
#define SA0_OFF 65536
#define SC_OFF  131072
#define SBC_OFF 172032
#define SMEM_LSTM 173056

// scratch layout inside SC region (floats)
#define SCR_W2  0
#define SCR_BN  1040
#define SCR_B   1104
#define SCR_RED 1168
#define SCR_W3  2192

__device__ __forceinline__ void bn_finalize_partial(const float* __restrict__ part,
                                                    float* s_red, int tid)
{
    if (tid < 128) {
        int f = tid & 31, p = tid >> 5;
        float s = 0.f, q = 0.f;
        const float* base = part + p * 32 * 64;
#pragma unroll 8
        for (int b = 0; b < 32; b++) { s += base[b * 64 + f]; q += base[b * 64 + 32 + f]; }
        s_red[p * 64 + f] = s;
        s_red[p * 64 + 32 + f] = q;
    }
}
__device__ __forceinline__ void bn_finalize_combine(const float* s_red,
                                                    const float* __restrict__ gamma,
                                                    const float* __restrict__ beta,
                                                    float* s_bn, int tid)
{
    if (tid < 32) {
        int f = tid;
        float s = 0.f, q = 0.f;
#pragma unroll
        for (int p = 0; p < 4; p++) { s += s_red[p * 64 + f]; q += s_red[p * 64 + 32 + f]; }
        float mean = s * (1.f / (float)BATCH);
        float var  = q * (1.f / (float)BATCH) - mean * mean;
        float sc   = gamma[f] * rsqrtf(var + 1e-5f);
        s_bn[f] = sc; s_bn[32 + f] = beta[f] - mean * sc;
    }
}

// stats reduce helper: a[32] (valid on q4==0 lanes), writes partials
__device__ __forceinline__ void stats_out(const float* a, int q4, float* s_red,
                                          float* __restrict__ gpart, int tid, int bx)
{
    int lane = tid & 31, warp = tid >> 5;
#pragma unroll
    for (int f = 0; f < 32; f++) {
        float sv = (q4 == 0) ? a[f] : 0.f;
        float qv = sv * a[f];
#pragma unroll
        for (int off = 16; off >= 1; off >>= 1) {
            sv += __shfl_xor_sync(0xffffffffu, sv, off);
            qv += __shfl_xor_sync(0xffffffffu, qv, off);
        }
        if (lane == 0) { s_red[warp * 64 + f] = sv; s_red[warp * 64 + 32 + f] = qv; }
    }
    __syncthreads();
    if (tid < 64) {
        float t = 0.f;
#pragma unroll
        for (int w = 0; w < 16; w++) t += s_red[w * 64 + tid];
        gpart[bx * 64 + tid] = t;
    }
}

// =====================================================================
// Fused kernel: MLP chain (smem-resident activations) + LSTM
// grid 128 x 512 threads
// =====================================================================
__global__ __launch_bounds__(512, 1)
void k_fused(const float* __restrict__ x0, const float* __restrict__ x1,
             const float* __restrict__ x2, const float* __restrict__ W1,
             const float* __restrict__ b1, const float* __restrict__ g1,
             const float* __restrict__ beta1, const float* __restrict__ W2,
             const float* __restrict__ b2, const float* __restrict__ g2,
             const float* __restrict__ beta2, const float* __restrict__ W3,
             const float* __restrict__ b3, const float* __restrict__ Wih,
             const float* __restrict__ Whh, const float* __restrict__ bih,
             const float* __restrict__ bhh, float* __restrict__ out)
{
    extern __shared__ u8 smem[];
    float* sW1  = (float*)(smem + SW_OFF);          // 12304 floats quarter-layout
    float* scr  = (float*)(smem + SC_OFF);
    float* sA1  = (float*)(smem + SA0_OFF);         // 128 x 32
    float* sA2  = (float*)(smem + SA0_OFF + 32768); // 128 x 32
    float* sBCf = (float*)(smem + SBC_OFF);
    float* sCf  = (float*)(smem + SC_OFF);          // LSTM c-state (phase D)

    int tid = threadIdx.x;
    int bx  = blockIdx.x;
    int q4  = tid & 3;
    int rowL = tid >> 2;                            // local row 0..127
    int row  = bx * 128 + rowL;

    // ============ Phase A: mlp1 + weight prep ============
    for (int i = tid; i < 12288; i += 512) {
        int h = i / 384, k = i - h * 384;
        int c = k >> 2, qq = c & 3, j = c >> 2;
        sW1[qq * 3076 + j * 128 + (k & 3) * 32 + h] = W1[i];
    }
    if (tid < 32) scr[SCR_B + tid] = b1[tid];
    {
        int gid = bx * 512 + tid;
        if (gid < 32768) prep_one(gid, Wih, Whh);
    }
    __syncthreads();

    {
        u64 acc[16];
#pragma unroll
        for (int i = 0; i < 16; i++) acc[i] = 0ull;
        const float4* px0 = (const float4*)(x0 + (size_t)row * NOUT);
        const float4* px1 = (const float4*)(x1 + (size_t)row * NOUT) - 32;
        const float4* px2 = (const float4*)(x2 + (size_t)row * NOUT) - 64;
        const ulonglong2* wb = (const ulonglong2*)sW1 + q4 * 769;
#pragma unroll 4
        for (int j = 0; j < 24; j++) {
            const float4* bp = (j < 8) ? px0 : (j < 16) ? px1 : px2;
            int i = 4 * j + q4;
            float4 xv = bp[i];
            const ulonglong2* wr = wb + j * 32;
#pragma unroll
            for (int c = 0; c < 4; c++) {
                float xc = (c == 0) ? xv.x : (c == 1) ? xv.y : (c == 2) ? xv.z : xv.w;
                u64 xp2 = pk2(xc, xc);
#pragma unroll
                for (int f = 0; f < 8; f++) {
                    ulonglong2 wv = wr[c * 8 + f];
                    ffma2(acc[2 * f], xp2, wv.x);
                    ffma2(acc[2 * f + 1], xp2, wv.y);
                }
            }
        }
#pragma unroll
        for (int f = 0; f < 16; f++) comb4(acc[f]);

        float a[32];
#pragma unroll
        for (int f = 0; f < 16; f++) upk2(acc[f], a[2 * f], a[2 * f + 1]);
#pragma unroll
        for (int f = 0; f < 32; f++) a[f] += scr[SCR_B + f];

        if (q4 == 0) {
            float4* outp = (float4*)(sA1 + rowL * 32);
#pragma unroll
            for (int i = 0; i < 8; i++)
                outp[i] = make_float4(a[4 * i], a[4 * i + 1], a[4 * i + 2], a[4 * i + 3]);
        }
        stats_out(a, q4, scr + SCR_RED, g_part1, tid, bx);
    }
    grid_sync(tid);

    // ============ Phase B: bn1 + mlp2 ============
    for (int i = tid; i < 1024; i += 512) {
        int h = i >> 5, k = i & 31;
        int qq = k >> 3, kl = k & 7;
        scr[SCR_W2 + qq * 260 + kl * 32 + h] = W2[i];
    }
    if (tid < 32) scr[SCR_B + tid] = b2[tid];
    bn_finalize_partial(g_part1, scr + SCR_RED, tid);
    __syncthreads();
    bn_finalize_combine(scr + SCR_RED, g1, beta1, scr + SCR_BN, tid);
    __syncthreads();

    {
        int kb = q4 * 8;
        float hv[8];
        const float4* ip = (const float4*)(sA1 + rowL * 32);
        const float* s_bn = scr + SCR_BN;
#pragma unroll
        for (int i = 0; i < 2; i++) {
            float4 v = ip[2 * q4 + i];
            int k0 = kb + 4 * i;
            hv[4 * i]     = fmaxf(fmaf(v.x, s_bn[k0],     s_bn[32 + k0]),     0.f);
            hv[4 * i + 1] = fmaxf(fmaf(v.y, s_bn[k0 + 1], s_bn[32 + k0 + 1]), 0.f);
            hv[4 * i + 2] = fmaxf(fmaf(v.z, s_bn[k0 + 2], s_bn[32 + k0 + 2]), 0.f);
            hv[4 * i + 3] = fmaxf(fmaf(v.w, s_bn[k0 + 3], s_bn[32 + k0 + 3]), 0.f);
        }
        u64 acc[16];
#pragma unroll
        for (int i = 0; i < 16; i++) acc[i] = 0ull;
        const ulonglong2* wb = (const ulonglong2*)(scr + SCR_W2) + q4 * 65;
#pragma unroll
        for (int k = 0; k < 8; k++) {
            u64 xp2 = pk2(hv[k], hv[k]);
            const ulonglong2* wr = wb + k * 8;
#pragma unroll
            for (int f = 0; f < 8; f++) {
                ulonglong2 wv = wr[f];
                ffma2(acc[2 * f], xp2, wv.x);
                ffma2(acc[2 * f + 1], xp2, wv.y);
            }
        }
#pragma unroll
        for (int f = 0; f < 16; f++) comb4(acc[f]);

        float a[32];
#pragma unroll
        for (int f = 0; f < 16; f++) upk2(acc[f], a[2 * f], a[2 * f + 1]);
#pragma unroll
        for (int f = 0; f < 32; f++) a[f] += scr[SCR_B + f];

        if (q4 == 0) {
            float4* outp = (float4*)(sA2 + rowL * 32);
#pragma unroll
            for (int i = 0; i < 8; i++)
                outp[i] = make_float4(a[4 * i], a[4 * i + 1], a[4 * i + 2], a[4 * i + 3]);
        }
        stats_out(a, q4, scr + SCR_RED, g_part2, tid, bx);
    }
    grid_sync(tid);

    // ============ Phase C: bn2 + mlp3 -> m-split into A-tile buf0 ============
    for (int i = tid; i < 2048; i += 512) {
        int j = i >> 5, k = i & 31;
        int qq = k >> 3, kl = k & 7;
        scr[SCR_W3 + qq * 516 + kl * 64 + j] = W3[i];
    }
    if (tid < 64) scr[SCR_B + tid] = b3[tid];
    bn_finalize_partial(g_part2, scr + SCR_RED, tid);
    __syncthreads();
    bn_finalize_combine(scr + SCR_RED, g2, beta2, scr + SCR_BN, tid);
    __syncthreads();

    {
        int kb = q4 * 8;
        float hv[8];
        const float4* ip = (const float4*)(sA2 + rowL * 32);
        const float* s_bn = scr + SCR_BN;
#pragma unroll
        for (int i = 0; i < 2; i++) {
            float4 v = ip[2 * q4 + i];
            int k0 = kb + 4 * i;
            hv[4 * i]     = fmaxf(fmaf(v.x, s_bn[k0],     s_bn[32 + k0]),     0.f);
            hv[4 * i + 1] = fmaxf(fmaf(v.y, s_bn[k0 + 1], s_bn[32 + k0 + 1]), 0.f);
            hv[4 * i + 2] = fmaxf(fmaf(v.z, s_bn[k0 + 2], s_bn[32 + k0 + 2]), 0.f);
            hv[4 * i + 3] = fmaxf(fmaf(v.w, s_bn[k0 + 3], s_bn[32 + k0 + 3]), 0.f);
        }
        u64 acc[32];
#pragma unroll
        for (int i = 0; i < 32; i++) acc[i] = 0ull;
        const ulonglong2* wb = (const ulonglong2*)(scr + SCR_W3) + q4 * 129;
#pragma unroll
        for (int k = 0; k < 8; k++) {
            u64 xp2 = pk2(hv[k], hv[k]);
            const ulonglong2* wr = wb + k * 16;
#pragma unroll
            for (int f = 0; f < 16; f++) {
                ulonglong2 wv = wr[f];
                ffma2(acc[2 * f], xp2, wv.x);
                ffma2(acc[2 * f + 1], xp2, wv.y);
            }
        }
#pragma unroll
        for (int f = 0; f < 32; f++) comb4(acc[f]);

        __syncthreads();   // sA2 reads done everywhere before buf0 writes? (buf0 != sA2; but sA1 overlap) -- buf0 overlaps sA1 (dead) only. Barrier orders stats scratch reuse.

        // m-split: this thread owns cols [q4*16, q4*16+16) of its row
        float v[16];
#pragma unroll
        for (int j = 0; j < 8; j++) {
            float a, b;
            upk2(acc[q4 * 8 + j], a, b);
            v[2 * j]     = a + scr[SCR_B + q4 * 16 + 2 * j];
            v[2 * j + 1] = b + scr[SCR_B + q4 * 16 + 2 * j + 1];
        }
        int rowbase = SA0_OFF + rowL * 256;
        int kbb = q4 * 32;
        int swz = (rowL & 7) << 4;
#pragma unroll
        for (int c4 = 0; c4 < 2; c4++) {
            uint4 hi4, lo4;
            u32* hp = (u32*)&hi4; u32* lp = (u32*)&lo4;
#pragma unroll
            for (int e = 0; e < 4; e++) {
                float a = v[c4 * 8 + 2 * e], b = v[c4 * 8 + 2 * e + 1];
                __nv_bfloat162 th = __floats2bfloat162_rn(a, b);
                float la = a - __bfloat162float(th.x);
                float lb = b - __bfloat162float(th.y);
                __nv_bfloat162 tl = __floats2bfloat162_rn(la, lb);
                hp[e] = *(u32*)&th;
                lp[e] = *(u32*)&tl;
            }
            int offh = rowbase + ((kbb + c4 * 16) ^ swz);
            *(uint4*)(smem + offh)       = hi4;
            *(uint4*)(smem + offh + 128) = lo4;
        }
    }

    // ============ Phase D: LSTM (R15 core) ============
    {
        uint4* d = (uint4*)(smem + SW_OFF);
        const uint4* s = (const uint4*)g_Wih_sw;
        for (int i = tid; i < 4096; i += 512) d[i] = s[i];
    }
    if (tid < 256) {
        int r = n_to_row(tid);
        sBCf[tid] = bih[r] + bhh[r];
    }
    __syncthreads();
    for (int i = tid; i < 512 * 20; i += 512) sCf[i] = 0.f;
    __syncthreads();

    int wid  = tid >> 5;
    int lane = tid & 31;
    int s0   = bx * 128;
    int warp_m = wid & 1;
    int warp_n = wid >> 1;
    int lane8 = lane & 7;
    u32 sbase = smem_u32(smem);

    int rA = warp_m * 64 + lane8 + (lane & 8);
    int kA8b = (lane & 16) ? 16 : 0;
    int swzA = (rA & 7) << 4;
    u32 aRow = sbase + SA0_OFF + (u32)(rA * 256);

    int rB = warp_n * 32 + lane8 + ((lane & 16) >> 1);
    int kB8b = (lane & 8) ? 16 : 0;
    int swzB = (rB & 7) << 4;
    u32 bRow = sbase + SW_OFF + (u32)(rB * 256);

    int g    = lane >> 2;
    int L4   = lane & 3;
    int cbase = tid * 20;
    int barid = 1 + warp_m;

    float bv[4][2];
#pragma unroll
    for (int gt = 0; gt < 4; gt++) {
        int nc = warp_n * 32 + gt * 8 + 2 * L4;
        bv[gt][0] = sBCf[nc];
        bv[gt][1] = sBCf[nc + 1];
    }

    int rowEa = warp_m * 64 + g;
    u32 qb    = (u32)(16 * warp_n + 4 * L4);
    u32 eoff  = qb ^ ((u32)g << 4);
    int qcol  = warp_n * 8 + 2 * L4;

#pragma unroll 1
    for (int t = 0; t < 26; t++) {
        u32 aBuf = aRow + ((t & 1) << 15);

        float acc[4][4][4];
#pragma unroll
        for (int mt = 0; mt < 4; mt++)
#pragma unroll
            for (int nt = 0; nt < 4; nt++)
#pragma unroll
                for (int e = 0; e < 4; e++) acc[mt][nt][e] = 0.f;

#pragma unroll
        for (int c = 0; c < 4; c++) {
            u32 afh[4][4], afl[4][4], bfh[2][4], bfl[2][4];
            u32 aoffh = (u32)((kA8b + 32 * c) ^ swzA);
            u32 aoffl = (u32)((kA8b + 32 * (c + 4)) ^ swzA);
            u32 boffh = (u32)((kB8b + 32 * c) ^ swzB);
            u32 boffl = (u32)((kB8b + 32 * (c + 4)) ^ swzB);
#pragma unroll
            for (int mt = 0; mt < 4; mt++)
                LDSM4(afh[mt][0], afh[mt][1], afh[mt][2], afh[mt][3],
                      aBuf + mt * 4096 + aoffh);
#pragma unroll
            for (int np = 0; np < 2; np++)
                LDSM4(bfh[np][0], bfh[np][1], bfh[np][2], bfh[np][3],
                      bRow + np * 4096 + boffh);
#pragma unroll
            for (int np = 0; np < 2; np++)
                LDSM4(bfl[np][0], bfl[np][1], bfl[np][2], bfl[np][3],
                      bRow + np * 4096 + boffl);
#pragma unroll
            for (int mt = 0; mt < 4; mt++)
#pragma unroll
                for (int np = 0; np < 2; np++) {
                    MMA16816(acc[mt][2 * np],     afh[mt][0], afh[mt][1], afh[mt][2], afh[mt][3],
                             bfh[np][0], bfh[np][1]);
                    MMA16816(acc[mt][2 * np + 1], afh[mt][0], afh[mt][1], afh[mt][2], afh[mt][3],
                             bfh[np][2], bfh[np][3]);
                }
#pragma unroll
            for (int mt = 0; mt < 4; mt++)
#pragma unroll
                for (int np = 0; np < 2; np++) {
                    MMA16816(acc[mt][2 * np],     afh[mt][0], afh[mt][1], afh[mt][2], afh[mt][3],
                             bfl[np][0], bfl[np][1]);
                    MMA16816(acc[mt][2 * np + 1], afh[mt][0], afh[mt][1], afh[mt][2], afh[mt][3],
                             bfl[np][2], bfl[np][3]);
                }
#pragma unroll
            for (int mt = 0; mt < 4; mt++)
                LDSM4(afl[mt][0], afl[mt][1], afl[mt][2], afl[mt][3],
                      aBuf + mt * 4096 + aoffl);
#pragma unroll
            for (int mt = 0; mt < 4; mt++)
#pragma unroll
                for (int np = 0; np < 2; np++) {
                    MMA16816(acc[mt][2 * np],     afl[mt][0], afl[mt][1], afl[mt][2], afl[mt][3],
                             bfh[np][0], bfh[np][1]);
                    MMA16816(acc[mt][2 * np + 1], afl[mt][0], afl[mt][1], afl[mt][2], afl[mt][3],
                             bfh[np][2], bfh[np][3]);
                }
        }

        u32 stBase = (u32)(SA0_OFF + (((t & 1) ^ 1) << 15)) + eoff;
#pragma unroll
        for (int mt = 0; mt < 4; mt++) {
            int rowA = rowEa + mt * 16;
            float4 cva = *(float4*)&sCf[cbase + mt * 4];
            float cc[4] = {cva.x, cva.y, cva.z, cva.w};
            float hres[4];
#pragma unroll
            for (int e = 0; e < 4; e++) {
                int eb = e & 1;
                float gi = acc[mt][0][e] + bv[0][eb];
                float gf = acc[mt][1][e] + bv[1][eb];
                float gg = acc[mt][2][e] + bv[2][eb];
                float go = acc[mt][3][e] + bv[3][eb];
                float si = fmaf(tanhfast(0.5f * gi), 0.5f, 0.5f);
                float sf = fmaf(tanhfast(0.5f * gf), 0.5f, 0.5f);
                float so = fmaf(tanhfast(0.5f * go), 0.5f, 0.5f);
                float tg = tanhfast(gg);
                float cn = fmaf(sf, cc[e], si * tg);
                cc[e] = cn;
                hres[e] = so * tanhfast(cn);
            }
            *(float4*)&sCf[cbase + mt * 4] = make_float4(cc[0], cc[1], cc[2], cc[3]);

            __nv_bfloat162 Ha = __floats2bfloat162_rn(hres[0], hres[1]);
            __nv_bfloat162 Hb = __floats2bfloat162_rn(hres[2], hres[3]);
            float la0 = hres[0] - __bfloat162float(Ha.x);
            float la1 = hres[1] - __bfloat162float(Ha.y);
            float lb0 = hres[2] - __bfloat162float(Hb.x);
            float lb1 = hres[3] - __bfloat162float(Hb.y);
            __nv_bfloat162 La = __floats2bfloat162_rn(la0, la1);
            __nv_bfloat162 Lb = __floats2bfloat162_rn(lb0, lb1);

            u32 addrA = stBase + (u32)(rowA * 256);
            u32 addrB = addrA + 2048;
            *(u32*)(smem + addrA)       = *(u32*)&Ha;
            *(u32*)(smem + addrA + 128) = *(u32*)&La;
            *(u32*)(smem + addrB)       = *(u32*)&Hb;
            *(u32*)(smem + addrB + 128) = *(u32*)&Lb;

            if (t >= 1) {
                size_t obase = ((size_t)(s0 + rowA) * NPRED + (t - 1)) * 64 + qcol;
                *(float2*)(out + obase) = make_float2(hres[0], hres[1]);
                *(float2*)(out + obase + (size_t)8 * NPRED * 64) = make_float2(hres[2], hres[3]);
            }
        }

        if (t == 0) {
            __syncthreads();
            uint4* d = (uint4*)(smem + SW_OFF);
            const uint4* src = (const uint4*)g_Wc_sw;
            for (int i = tid; i < 4096; i += 512) d[i] = src[i];
            __syncthreads();
        } else {
            BAR_HALF(barid);
        }
    }
}

// =====================================================================
extern "C" void kernel_launch(void* const* d_in, const int* in_sizes, int n_in,
                              void* d_out, int out_size)
{
    const float* x0    = (const float*)d_in[0];
    const float* x1    = (const float*)d_in[1];
    const float* x2    = (const float*)d_in[2];
    const float* W1    = (const float*)d_in[3];
    const float* b1    = (const float*)d_in[4];
    const float* g1    = (const float*)d_in[5];
    const float* beta1 = (const float*)d_in[6];
    const float* W2    = (const float*)d_in[7];
    const float* b2    = (const float*)d_in[8];
    const float* g2    = (const float*)d_in[9];
    const float* beta2 = (const float*)d_in[10];
    const float* W3    = (const float*)d_in[11];
    const float* b3    = (const float*)d_in[12];
    const float* Wih   = (const float*)d_in[13];
    const float* Whh   = (const float*)d_in[14];
    const float* bih   = (const float*)d_in[15];
    const float* bhh   = (const float*)d_in[16];
    float* out = (float*)d_out;

    cudaFuncSetAttribute(k_fused, cudaFuncAttributeMaxDynamicSharedMemorySize, SMEM_LSTM);

    k_fused<<<128, 512, SMEM_LSTM>>>(x0, x1, x2, W1, b1, g1, beta1,
                                     W2, b2, g2, beta2, W3, b3,
                                     Wih, Whh, bih, bhh, out);
}